// round 2
// baseline (speedup 1.0000x reference)
#include <cuda_runtime.h>

#define N_MAX     1048576
#define SEGS      (64 * 4096)   // 262144 segments
#define GRID_DIM  64
#define NUM_CELLS 4096
#define CCH       64            // channels

// ---- scratch (static device globals; no runtime allocation) ----
__device__ int g_idx[N_MAX];        // per-point cell index
__device__ int g_pids[N_MAX];       // point ids sorted by cell
__device__ int g_counts[SEGS];      // points per cell
__device__ int g_offsets[SEGS];     // exclusive prefix of counts
__device__ int g_cursor[SEGS];      // running write cursor for scatter
__device__ int g_blocksums[256];    // scan partials

// ---------------------------------------------------------------
__global__ void k_zero() {
    int i = blockIdx.x * blockDim.x + threadIdx.x;
    if (i < SEGS) g_counts[i] = 0;
}

// pos/batch are int32 (JAX x64 disabled => int64 request materializes int32)
__global__ void k_hist(const int2* __restrict__ pos,
                       const int* __restrict__ batch, int n) {
    int i = blockIdx.x * blockDim.x + threadIdx.x;
    if (i >= n) return;
    int2 p = pos[i];
    int idx = batch[i] * NUM_CELLS
            + (p.x >> 2) * GRID_DIM
            + (p.y >> 2);
    g_idx[i] = idx;
    atomicAdd(&g_counts[idx], 1);
}

// block-level exclusive scan over 1024 elements per block
__global__ void k_scan1() {
    int i    = blockIdx.x * 1024 + threadIdx.x;
    int lane = threadIdx.x & 31;
    int wid  = threadIdx.x >> 5;
    int v    = g_counts[i];
    int incl = v;
    #pragma unroll
    for (int d = 1; d < 32; d <<= 1) {
        int u = __shfl_up_sync(0xffffffffu, incl, d);
        if (lane >= d) incl += u;
    }
    __shared__ int ws[32];
    __shared__ int wexcl[32];
    if (lane == 31) ws[wid] = incl;
    __syncthreads();
    if (wid == 0) {
        int w = ws[lane];
        int wi = w;
        #pragma unroll
        for (int d = 1; d < 32; d <<= 1) {
            int u = __shfl_up_sync(0xffffffffu, wi, d);
            if (lane >= d) wi += u;
        }
        wexcl[lane] = wi - w;
        if (lane == 31) g_blocksums[blockIdx.x] = wi;   // block total
    }
    __syncthreads();
    g_offsets[i] = incl - v + wexcl[wid];
}

// exclusive scan of the 256 block totals (single block, 256 threads)
__global__ void k_scan2() {
    int t    = threadIdx.x;
    int lane = t & 31;
    int wid  = t >> 5;
    int v    = g_blocksums[t];
    int incl = v;
    #pragma unroll
    for (int d = 1; d < 32; d <<= 1) {
        int u = __shfl_up_sync(0xffffffffu, incl, d);
        if (lane >= d) incl += u;
    }
    __shared__ int ws[8];
    __shared__ int wexcl[8];
    if (lane == 31) ws[wid] = incl;
    __syncthreads();
    if (t < 8) {
        int w = ws[t];
        int wi = w;
        #pragma unroll
        for (int d = 1; d < 8; d <<= 1) {
            int u = __shfl_up_sync(0x000000ffu, wi, d);
            if (t >= d) wi += u;
        }
        wexcl[t] = wi - w;
    }
    __syncthreads();
    g_blocksums[t] = incl - v + wexcl[wid];
}

__global__ void k_scan3() {
    int i = blockIdx.x * 1024 + threadIdx.x;
    int o = g_offsets[i] + g_blocksums[blockIdx.x];
    g_offsets[i] = o;
    g_cursor[i]  = o;
}

__global__ void k_scatter(int n) {
    int i = blockIdx.x * blockDim.x + threadIdx.x;
    if (i >= n) return;
    int idx = g_idx[i];
    int p = atomicAdd(&g_cursor[idx], 1);
    g_pids[p] = i;
}

// one warp per cell; lane l owns channels [2l, 2l+1] as a float2.
// pids for the cell are loaded cooperatively (one coalesced LDG) and
// broadcast via shfl, removing the serial pid->row latency chain.
__global__ void k_gather(const float2* __restrict__ x2, float2* __restrict__ out2) {
    int warp = (blockIdx.x * blockDim.x + threadIdx.x) >> 5;
    int lane = threadIdx.x & 31;
    if (warp >= SEGS) return;

    int count = g_counts[warp];
    int start = g_offsets[warp];

    float2 acc;
    if (count == 0) {
        acc.x = 0.0f; acc.y = 0.0f;
    } else {
        const float ninf = __int_as_float(0xff800000);
        acc.x = ninf; acc.y = ninf;

        int c0 = count < 32 ? count : 32;
        int mypid = (lane < c0) ? g_pids[start + lane] : 0;
        for (int j = 0; j < c0; j++) {
            int pid = __shfl_sync(0xffffffffu, mypid, j);
            float2 v = x2[pid * 32 + lane];       // 256B coalesced row read
            acc.x = fmaxf(acc.x, v.x);
            acc.y = fmaxf(acc.y, v.y);
        }
        for (int j = 32; j < count; j++) {        // (practically never taken)
            int pid = g_pids[start + j];
            float2 v = x2[pid * 32 + lane];
            acc.x = fmaxf(acc.x, v.x);
            acc.y = fmaxf(acc.y, v.y);
        }
    }
    out2[warp * 32 + lane] = acc;                 // 256B coalesced write
}

// ---------------------------------------------------------------
extern "C" void kernel_launch(void* const* d_in, const int* in_sizes, int n_in,
                              void* d_out, int out_size) {
    const float* x     = (const float*)d_in[0];
    const int2*  pos   = (const int2*)d_in[1];
    const int*   batch = (const int*)d_in[2];
    float* out = (float*)d_out;
    int n = in_sizes[2];     // number of points (batch has N elements)

    k_zero   <<<SEGS / 256, 256>>>();
    k_hist   <<<(n + 255) / 256, 256>>>(pos, batch, n);
    k_scan1  <<<SEGS / 1024, 1024>>>();
    k_scan2  <<<1, 256>>>();
    k_scan3  <<<SEGS / 1024, 1024>>>();
    k_scatter<<<(n + 255) / 256, 256>>>(n);
    k_gather <<<SEGS / 8, 256>>>((const float2*)x, (float2*)out);
}

// round 3
// speedup vs baseline: 1.0113x; 1.0113x over previous
#include <cuda_runtime.h>

#define N_MAX     1048576
#define SEGS      (64 * 4096)   // 262144 segments
#define GRID_DIM  64
#define NUM_CELLS 4096

// ---- scratch (static device globals; no runtime allocation) ----
__device__ int g_idx[N_MAX];        // per-point cell index
__device__ int g_pids[N_MAX];       // point ids sorted by cell
__device__ int g_counts[SEGS];      // points per cell
__device__ int g_offsets[SEGS];     // exclusive prefix of counts
__device__ int g_cursor[SEGS];      // running write cursor for scatter
__device__ int g_blocksums[256];    // scan partials

// ---------------------------------------------------------------
__global__ void k_zero() {
    int i = blockIdx.x * blockDim.x + threadIdx.x;
    if (i < SEGS) g_counts[i] = 0;
}

// pos/batch are int32 (JAX x64 disabled => int64 request materializes int32)
__global__ void k_hist(const int2* __restrict__ pos,
                       const int* __restrict__ batch, int n) {
    int i = blockIdx.x * blockDim.x + threadIdx.x;
    if (i >= n) return;
    int2 p = pos[i];
    int idx = batch[i] * NUM_CELLS
            + (p.x >> 2) * GRID_DIM
            + (p.y >> 2);
    g_idx[i] = idx;
    atomicAdd(&g_counts[idx], 1);
}

// block-level exclusive scan over 1024 elements per block; emits block totals
__global__ void k_scan1() {
    int i    = blockIdx.x * 1024 + threadIdx.x;
    int lane = threadIdx.x & 31;
    int wid  = threadIdx.x >> 5;
    int v    = g_counts[i];
    int incl = v;
    #pragma unroll
    for (int d = 1; d < 32; d <<= 1) {
        int u = __shfl_up_sync(0xffffffffu, incl, d);
        if (lane >= d) incl += u;
    }
    __shared__ int ws[32];
    __shared__ int wexcl[32];
    if (lane == 31) ws[wid] = incl;
    __syncthreads();
    if (wid == 0) {
        int w = ws[lane];
        int wi = w;
        #pragma unroll
        for (int d = 1; d < 32; d <<= 1) {
            int u = __shfl_up_sync(0xffffffffu, wi, d);
            if (lane >= d) wi += u;
        }
        wexcl[lane] = wi - w;
        if (lane == 31) g_blocksums[blockIdx.x] = wi;   // block total
    }
    __syncthreads();
    g_offsets[i] = incl - v + wexcl[wid];
}

// fused: each block derives its exclusive base from the 256 partials (L2-hot),
// then adds back and initializes cursors. Replaces old scan2 + scan3.
__global__ void k_scanB() {
    __shared__ int base_s;
    int t = threadIdx.x;
    if (t < 32) {
        int sum = 0;
        for (int j = t; j < blockIdx.x; j += 32) sum += g_blocksums[j];
        #pragma unroll
        for (int d = 16; d; d >>= 1) sum += __shfl_xor_sync(0xffffffffu, sum, d);
        if (t == 0) base_s = sum;
    }
    __syncthreads();
    int i = blockIdx.x * 1024 + t;
    int o = g_offsets[i] + base_s;
    g_offsets[i] = o;
    g_cursor[i]  = o;
}

__global__ void k_scatter(int n) {
    int i = blockIdx.x * blockDim.x + threadIdx.x;
    if (i >= n) return;
    int idx = g_idx[i];
    int p = atomicAdd(&g_cursor[idx], 1);
    g_pids[p] = i;
}

// one warp per cell. Lanes 0-15 process even points, lanes 16-31 odd points,
// each lane holding 4 channels (float4). Groups combined via shfl_xor(16).
__global__ void k_gather(const float4* __restrict__ x4, float4* __restrict__ out4) {
    int warp = (blockIdx.x * blockDim.x + threadIdx.x) >> 5;
    int lane = threadIdx.x & 31;
    if (warp >= SEGS) return;

    int count = g_counts[warp];
    int start = g_offsets[warp];
    int g = lane >> 4;          // point-pair group
    int s = lane & 15;          // float4 column within row

    float4 acc = make_float4(0.f, 0.f, 0.f, 0.f);
    if (count > 0) {
        const float ninf = __int_as_float(0xff800000);
        acc = make_float4(ninf, ninf, ninf, ninf);

        int c0 = count < 32 ? count : 32;
        int mypid = (lane < c0) ? g_pids[start + lane] : 0;
        for (int j = 0; j < c0; j += 2) {
            int jj = j + g; if (jj >= c0) jj = c0 - 1;    // odd tail: dup last
            int pid = __shfl_sync(0xffffffffu, mypid, jj);
            float4 v = x4[pid * 16 + s];                  // 256B row, 2 points/iter
            acc.x = fmaxf(acc.x, v.x);
            acc.y = fmaxf(acc.y, v.y);
            acc.z = fmaxf(acc.z, v.z);
            acc.w = fmaxf(acc.w, v.w);
        }
        for (int j = 32; j < count; j += 2) {             // practically never taken
            int jj = j + g; if (jj >= count) jj = count - 1;
            int pid = g_pids[start + jj];
            float4 v = x4[pid * 16 + s];
            acc.x = fmaxf(acc.x, v.x);
            acc.y = fmaxf(acc.y, v.y);
            acc.z = fmaxf(acc.z, v.z);
            acc.w = fmaxf(acc.w, v.w);
        }
        // combine the two point-groups (channels align across lane^16)
        acc.x = fmaxf(acc.x, __shfl_xor_sync(0xffffffffu, acc.x, 16));
        acc.y = fmaxf(acc.y, __shfl_xor_sync(0xffffffffu, acc.y, 16));
        acc.z = fmaxf(acc.z, __shfl_xor_sync(0xffffffffu, acc.z, 16));
        acc.w = fmaxf(acc.w, __shfl_xor_sync(0xffffffffu, acc.w, 16));
    }
    if (lane < 16) out4[warp * 16 + lane] = acc;          // 256B STG.128 row
}

// ---------------------------------------------------------------
extern "C" void kernel_launch(void* const* d_in, const int* in_sizes, int n_in,
                              void* d_out, int out_size) {
    const float* x     = (const float*)d_in[0];
    const int2*  pos   = (const int2*)d_in[1];
    const int*   batch = (const int*)d_in[2];
    float* out = (float*)d_out;
    int n = in_sizes[2];     // number of points

    k_zero   <<<SEGS / 256, 256>>>();
    k_hist   <<<(n + 255) / 256, 256>>>(pos, batch, n);
    k_scan1  <<<SEGS / 1024, 1024>>>();
    k_scanB  <<<SEGS / 1024, 1024>>>();
    k_scatter<<<(n + 255) / 256, 256>>>(n);
    k_gather <<<SEGS / 8, 256>>>((const float4*)x, (float4*)out);
}